// round 11
// baseline (speedup 1.0000x reference)
#include <cuda_runtime.h>
#include <cuda_bf16.h>
#include <cstdint>

#define BB 2
#define HH 32
#define SS 16384
#define DD 64
#define NHEADS (BB*HH)
#define SPLIT 16
#define CHUNK (SS/SPLIT)   /* 1024 s-rows per phase1 CTA */
#define NIT (CHUNK/64)     /* 16 staging iterations */

/* phase2 config */
#define TM 64                         /* s-rows per tile */
#define TILES_PER_HEAD (SS / TM)      /* 256 */
#define TIT 16                        /* tiles per CTA */
#define GRID2 (NHEADS * TILES_PER_HEAD / TIT)  /* 1024 */

/* scratch (no runtime alloc) */
__device__ float g_part[(size_t)NHEADS * SPLIT * 4160];
__device__ float g_norm[(size_t)NHEADS * 64];
__device__ __nv_bfloat16 g_memT_hi[(size_t)NHEADS * 4096];  /* [head][dv*64+dk] */
__device__ __nv_bfloat16 g_memT_lo[(size_t)NHEADS * 4096];

__device__ __forceinline__ float elu1(float x) {
    return x > 0.0f ? x + 1.0f : __expf(x);
}

__device__ __forceinline__ uint32_t smem_u32(const void* p) {
    uint32_t a;
    asm("{ .reg .u64 t; cvta.to.shared.u64 t, %1; cvt.u32.u64 %0, t; }" : "=r"(a) : "l"(p));
    return a;
}
__device__ __forceinline__ void cp_async16(uint32_t saddr, const void* gaddr) {
    asm volatile("cp.async.cg.shared.global [%0], [%1], 16;"
                 :: "r"(saddr), "l"(gaddr) : "memory");
}
#define CP_COMMIT() asm volatile("cp.async.commit_group;" ::: "memory")
#define CP_WAIT0()  asm volatile("cp.async.wait_group 0;" ::: "memory")

__device__ __forceinline__ void ldsm_x4(uint32_t& r0, uint32_t& r1, uint32_t& r2,
                                        uint32_t& r3, uint32_t addr) {
    asm volatile("ldmatrix.sync.aligned.m8n8.x4.shared.b16 {%0,%1,%2,%3}, [%4];"
                 : "=r"(r0), "=r"(r1), "=r"(r2), "=r"(r3) : "r"(addr));
}
__device__ __forceinline__ void ldsm_x4_t(uint32_t& r0, uint32_t& r1, uint32_t& r2,
                                          uint32_t& r3, uint32_t addr) {
    asm volatile("ldmatrix.sync.aligned.m8n8.x4.trans.shared.b16 {%0,%1,%2,%3}, [%4];"
                 : "=r"(r0), "=r"(r1), "=r"(r2), "=r"(r3) : "r"(addr));
}
__device__ __forceinline__ void mma_bf16(float* d, const uint32_t* a,
                                         uint32_t b0, uint32_t b1) {
    asm volatile(
        "mma.sync.aligned.m16n8k16.row.col.f32.bf16.bf16.f32 "
        "{%0,%1,%2,%3}, {%4,%5,%6,%7}, {%8,%9}, {%0,%1,%2,%3};"
        : "+f"(d[0]), "+f"(d[1]), "+f"(d[2]), "+f"(d[3])
        : "r"(a[0]), "r"(a[1]), "r"(a[2]), "r"(a[3]), "r"(b0), "r"(b1));
}

/* swizzled byte offset: 128B rows, 16B units XOR'ed by row&7 */
#define ASWZ(row, unit) (((uint32_t)(row) << 7) + ((((unit) ^ ((row) & 7)) & 7) << 4))

__device__ __forceinline__ uint32_t pack_bf16x2(float lo_val, float hi_val) {
    uint32_t r;
    asm("cvt.rn.bf16x2.f32 %0, %1, %2;" : "=r"(r) : "f"(hi_val), "f"(lo_val));
    return r;
}
__device__ __forceinline__ void split_store(char* hi, char* lo, float4 v,
                                            uint32_t off) {
    uint32_t h0 = pack_bf16x2(v.x, v.y);
    uint32_t h1 = pack_bf16x2(v.z, v.w);
    float hx = __uint_as_float(h0 << 16);
    float hy = __uint_as_float(h0 & 0xffff0000u);
    float hz = __uint_as_float(h1 << 16);
    float hw = __uint_as_float(h1 & 0xffff0000u);
    uint32_t l0 = pack_bf16x2(v.x - hx, v.y - hy);
    uint32_t l1 = pack_bf16x2(v.z - hz, v.w - hw);
    *(uint2*)(hi + off) = make_uint2(h0, h1);
    *(uint2*)(lo + off) = make_uint2(l0, l1);
}

/* ============ Phase 1: M = kf^T @ v, cp.async raw staging, 3 CTA/SM ============ */
/* dynamic smem layout */
#define P1_RAWK 0
#define P1_RAWV 16384
#define P1_KH   32768
#define P1_KL   40960
#define P1_VH   49152
#define P1_VL   57344
#define P1_NRM  65536                  /* float[256][4] */
#define P1_TOTAL (65536 + 4096)

__global__ void __launch_bounds__(256, 3)
phase1_mma(const float* __restrict__ kk, const float* __restrict__ vv) {
    extern __shared__ __align__(128) char dyn[];

    const int bx    = blockIdx.x;
    const int head  = bx / SPLIT;
    const int chunk = bx % SPLIT;
    const int tid   = threadIdx.x;
    const int wid   = tid >> 5;
    const int lane  = tid & 31;
    const int mi    = wid >> 1;       /* dk m-tile 0..3 */
    const int nh    = wid & 1;        /* dv half 0..1 */

    const uint32_t sb  = smem_u32(dyn);
    const uint32_t aKH = sb + P1_KH, aKL = sb + P1_KL;
    const uint32_t aVH = sb + P1_VH, aVL = sb + P1_VL;

    /* per-thread staging slots (fixed) */
    uint32_t soff[4];
    #pragma unroll
    for (int p = 0; p < 4; ++p) {
        int f = tid + p * 256;
        int c4 = (f & 15) * 4;
        soff[p] = ASWZ(f >> 4, c4 >> 3) + ((c4 >> 2) & 1) * 8;
    }
    const float* kbase = kk + ((size_t)head * SS + (size_t)chunk * CHUNK) * DD;
    const float* vbase = vv + ((size_t)head * SS + (size_t)chunk * CHUNK) * DD;

    float acc[4][4] = {};
    float nrm[4]    = {};

    /* issue cp.async for block 0 */
    #pragma unroll
    for (int p = 0; p < 4; ++p) {
        int f = tid + p * 256;
        cp_async16(sb + P1_RAWK + f * 16, kbase + f * 4);
        cp_async16(sb + P1_RAWV + f * 16, vbase + f * 4);
    }
    CP_COMMIT();

    for (int it = 0; it < NIT; ++it) {
        CP_WAIT0();
        __syncthreads();   /* raw(it) ready; prev mma done with bf16 */

        /* convert raw -> bf16 hi/lo (elu on K), accumulate norm */
        #pragma unroll
        for (int p = 0; p < 4; ++p) {
            int f = tid + p * 256;
            float4 kf = ((const float4*)(dyn + P1_RAWK))[f];
            kf.x = elu1(kf.x); kf.y = elu1(kf.y); kf.z = elu1(kf.z); kf.w = elu1(kf.w);
            nrm[0] += kf.x; nrm[1] += kf.y; nrm[2] += kf.z; nrm[3] += kf.w;
            split_store(dyn + P1_KH, dyn + P1_KL, kf, soff[p]);
            float4 vf = ((const float4*)(dyn + P1_RAWV))[f];
            split_store(dyn + P1_VH, dyn + P1_VL, vf, soff[p]);
        }
        __syncthreads();   /* bf16 ready; raw free */

        /* stage next block — overlaps the mma section */
        if (it + 1 < NIT) {
            const float* kn = kbase + (size_t)(it + 1) * 64 * DD;
            const float* vn = vbase + (size_t)(it + 1) * 64 * DD;
            #pragma unroll
            for (int p = 0; p < 4; ++p) {
                int f = tid + p * 256;
                cp_async16(sb + P1_RAWK + f * 16, kn + f * 4);
                cp_async16(sb + P1_RAWV + f * 16, vn + f * 4);
            }
            CP_COMMIT();
        }

        #pragma unroll
        for (int ps = 0; ps < 3; ++ps) {
            const uint32_t ab = (ps == 2) ? aKL : aKH;
            const uint32_t bb = (ps == 1) ? aVL : aVH;
            #pragma unroll
            for (int kt = 0; kt < 4; ++kt) {
                uint32_t a[4];
                {
                    int ar = kt * 16 + (lane & 7) + ((lane >> 4) << 3);
                    int au = mi * 2 + ((lane >> 3) & 1);
                    ldsm_x4_t(a[0], a[1], a[2], a[3], ab + ASWZ(ar, au));
                }
                uint32_t b[4][2];
                #pragma unroll
                for (int np = 0; np < 2; ++np) {
                    int br = kt * 16 + (lane & 7) + (((lane >> 3) & 1) << 3);
                    int bu = nh * 4 + np * 2 + (lane >> 4);
                    uint32_t r0, r1, r2, r3;
                    ldsm_x4_t(r0, r1, r2, r3, bb + ASWZ(br, bu));
                    b[np*2+0][0] = r0; b[np*2+0][1] = r1;
                    b[np*2+1][0] = r2; b[np*2+1][1] = r3;
                }
                #pragma unroll
                for (int nt = 0; nt < 4; ++nt)
                    mma_bf16(acc[nt], a, b[nt][0], b[nt][1]);
            }
        }
    }

    /* write M partial */
    float* outp = g_part + (size_t)bx * 4160;
    {
        int r_lo = mi * 16 + (lane >> 2);
        int r_hi = r_lo + 8;
        int c0   = nh * 32 + (lane & 3) * 2;
        #pragma unroll
        for (int nt = 0; nt < 4; ++nt) {
            *(float2*)&outp[r_lo * 64 + nt * 8 + c0] = make_float2(acc[nt][0], acc[nt][1]);
            *(float2*)&outp[r_hi * 64 + nt * 8 + c0] = make_float2(acc[nt][2], acc[nt][3]);
        }
    }
    /* norm: deterministic cross-thread reduction */
    float* snrm = (float*)(dyn + P1_NRM);
    snrm[tid*4+0] = nrm[0]; snrm[tid*4+1] = nrm[1];
    snrm[tid*4+2] = nrm[2]; snrm[tid*4+3] = nrm[3];
    __syncthreads();
    if (tid < 16) {
        float s0 = 0.f, s1 = 0.f, s2 = 0.f, s3 = 0.f;
        #pragma unroll
        for (int g = 0; g < 16; ++g) {
            s0 += snrm[(tid + 16*g)*4+0]; s1 += snrm[(tid + 16*g)*4+1];
            s2 += snrm[(tid + 16*g)*4+2]; s3 += snrm[(tid + 16*g)*4+3];
        }
        *(float4*)&outp[4096 + tid * 4] = make_float4(s0, s1, s2, s3);
    }
}

/* ------- Reduce: sum SPLIT partials; emit transposed bf16 hi/lo + fp32 norm ------- */
__global__ void __launch_bounds__(512) reduce_k() {
    const int head = blockIdx.x;
    for (int e = threadIdx.x; e < 4160; e += 512) {
        float s = 0.f;
        #pragma unroll
        for (int c = 0; c < SPLIT; ++c)
            s += g_part[((size_t)head * SPLIT + c) * 4160 + e];
        if (e < 4096) {
            int dk = e >> 6, dv = e & 63;
            __nv_bfloat16 h = __float2bfloat16(s);
            __nv_bfloat16 l = __float2bfloat16(s - __bfloat162float(h));
            g_memT_hi[(size_t)head * 4096 + dv * 64 + dk] = h;
            g_memT_lo[(size_t)head * 4096 + dv * 64 + dk] = l;
        } else {
            g_norm[(size_t)head * 64 + (e - 4096)] = s;
        }
    }
}

/* ============ Phase 2: Out = Qf @ M^T, cp.async raw staging, 3 CTA/SM ============ */
#define P2_RAWQ 0
#define P2_AH   16384
#define P2_AL   24576
#define P2_BH   32768
#define P2_BL   40960
#define P2_DEN  49152                 /* float[64] */
#define P2_TOTAL (49152 + 256)

__global__ void __launch_bounds__(256, 3)
phase2_mma(const float* __restrict__ q, float* __restrict__ outg) {
    extern __shared__ __align__(128) char dyn[];

    const int tid  = threadIdx.x;
    const int wid  = tid >> 5;
    const int lane = tid & 31;
    const int mi   = wid >> 1;        /* m-tile 0..3 */
    const int nh   = wid & 1;         /* n-half 0..1 */

    const uint32_t sb  = smem_u32(dyn);
    const uint32_t aAH = sb + P2_AH, aAL = sb + P2_AL;
    const uint32_t aBH = sb + P2_BH, aBL = sb + P2_BL;
    float* sden = (float*)(dyn + P2_DEN);

    const int t0   = blockIdx.x * TIT;
    const int head = t0 / TILES_PER_HEAD;

    /* ---- per-CTA: memory matrix (bf16 hi/lo, swizzled) ---- */
    {
        const __nv_bfloat16* bh = g_memT_hi + (size_t)head * 4096;
        const __nv_bfloat16* bl = g_memT_lo + (size_t)head * 4096;
        #pragma unroll
        for (int p = 0; p < 2; ++p) {
            int f = tid + p * 256;
            int r = f >> 3;
            int u = f & 7;
            uint32_t off = ASWZ(r, u);
            *(uint4*)(dyn + P2_BH + off) = *(const uint4*)(bh + r * 64 + u * 8);
            *(uint4*)(dyn + P2_BL + off) = *(const uint4*)(bl + r * 64 + u * 8);
        }
    }

    /* per-thread staging slots (fixed) */
    int srow[4]; uint32_t soff[4];
    #pragma unroll
    for (int p = 0; p < 4; ++p) {
        int f = tid + p * 256;
        srow[p] = f >> 4;
        int c4 = (f & 15) * 4;
        soff[p] = ASWZ(srow[p], c4 >> 3) + ((c4 >> 2) & 1) * 8;
    }
    const float4 mynrm = *(const float4*)(g_norm + (size_t)head * 64 + (tid & 15) * 4);
    const float* qhead = q + ((size_t)head * SS) * DD;

    /* issue cp.async for tile 0 */
    {
        const float* qblk = qhead + (size_t)((t0 % TILES_PER_HEAD) * TM) * DD;
        #pragma unroll
        for (int p = 0; p < 4; ++p) {
            int f = tid + p * 256;
            cp_async16(sb + P2_RAWQ + f * 16, qblk + f * 4);
        }
        CP_COMMIT();
    }

    for (int it = 0; it < TIT; ++it) {
        const int s0 = ((t0 + it) % TILES_PER_HEAD) * TM;

        CP_WAIT0();
        __syncthreads();   /* rawQ(it) ready; prev mma done with A/sden */

        /* ---- convert + fused denominator (fp32, deterministic shfl tree) ---- */
        #pragma unroll
        for (int p = 0; p < 4; ++p) {
            int f = tid + p * 256;
            float4 v = ((const float4*)(dyn + P2_RAWQ))[f];
            v.x = elu1(v.x); v.y = elu1(v.y); v.z = elu1(v.z); v.w = elu1(v.w);
            split_store(dyn + P2_AH, dyn + P2_AL, v, soff[p]);
            float dp = v.x * mynrm.x + v.y * mynrm.y + v.z * mynrm.z + v.w * mynrm.w;
            dp += __shfl_xor_sync(0xffffffffu, dp, 1);
            dp += __shfl_xor_sync(0xffffffffu, dp, 2);
            dp += __shfl_xor_sync(0xffffffffu, dp, 4);
            dp += __shfl_xor_sync(0xffffffffu, dp, 8);
            if ((lane & 15) == 0) sden[srow[p]] = dp;
        }
        __syncthreads();   /* A/sden ready; rawQ free */

        /* stage next tile — overlaps mma + epilogue */
        if (it + 1 < TIT) {
            const float* qblk =
                qhead + (size_t)(((t0 + it + 1) % TILES_PER_HEAD) * TM) * DD;
            #pragma unroll
            for (int p = 0; p < 4; ++p) {
                int f = tid + p * 256;
                cp_async16(sb + P2_RAWQ + f * 16, qblk + f * 4);
            }
            CP_COMMIT();
        }

        /* ---- 3-pass bf16 mma: hh + hl + lh ---- */
        float acc[4][4];
        #pragma unroll
        for (int nt = 0; nt < 4; ++nt)
            #pragma unroll
            for (int e = 0; e < 4; ++e) acc[nt][e] = 0.f;

        #pragma unroll
        for (int ps = 0; ps < 3; ++ps) {
            const uint32_t abase = (ps == 2) ? aAL : aAH;
            const uint32_t bbase = (ps == 1) ? aBL : aBH;
            #pragma unroll
            for (int kt = 0; kt < 4; ++kt) {
                uint32_t a[4];
                {
                    int ar = mi * 16 + (lane & 15);
                    ldsm_x4(a[0], a[1], a[2], a[3],
                            abase + ASWZ(ar, kt * 2 + (lane >> 4)));
                }
                uint32_t b[4][2];
                #pragma unroll
                for (int np = 0; np < 2; ++np) {
                    int br = nh * 32 + np * 16 + (lane & 7) + ((lane >> 4) << 3);
                    uint32_t r0, r1, r2, r3;
                    ldsm_x4(r0, r1, r2, r3,
                            bbase + ASWZ(br, kt * 2 + ((lane >> 3) & 1)));
                    b[np*2+0][0] = r0; b[np*2+0][1] = r1;
                    b[np*2+1][0] = r2; b[np*2+1][1] = r3;
                }
                #pragma unroll
                for (int nt = 0; nt < 4; ++nt)
                    mma_bf16(acc[nt], a, b[nt][0], b[nt][1]);
            }
        }

        /* ---- epilogue: divide, store ---- */
        int r_lo = mi * 16 + (lane >> 2);
        int r_hi = r_lo + 8;
        float inv_lo = 1.0f / sden[r_lo];
        float inv_hi = 1.0f / sden[r_hi];
        float* obase = outg + ((size_t)head * SS + (size_t)s0) * DD;
        int c0 = nh * 32 + (lane & 3) * 2;
        #pragma unroll
        for (int nt = 0; nt < 4; ++nt) {
            *(float2*)(obase + (size_t)r_lo * DD + nt * 8 + c0) =
                make_float2(acc[nt][0] * inv_lo, acc[nt][1] * inv_lo);
            *(float2*)(obase + (size_t)r_hi * DD + nt * 8 + c0) =
                make_float2(acc[nt][2] * inv_hi, acc[nt][3] * inv_hi);
        }
    }
}

extern "C" void kernel_launch(void* const* d_in, const int* in_sizes, int n_in,
                              void* d_out, int out_size) {
    const float* q = (const float*)d_in[0];
    const float* k = (const float*)d_in[1];
    const float* v = (const float*)d_in[2];
    float* out = (float*)d_out;

    cudaFuncSetAttribute(phase1_mma, cudaFuncAttributeMaxDynamicSharedMemorySize,
                         P1_TOTAL);
    cudaFuncSetAttribute(phase2_mma, cudaFuncAttributeMaxDynamicSharedMemorySize,
                         P2_TOTAL);

    phase1_mma<<<NHEADS * SPLIT, 256, P1_TOTAL>>>(k, v);
    reduce_k<<<NHEADS, 512>>>();
    phase2_mma<<<GRID2, 256, P2_TOTAL>>>(q, out);
}

// round 12
// speedup vs baseline: 1.1191x; 1.1191x over previous
#include <cuda_runtime.h>
#include <cuda_bf16.h>
#include <cstdint>

#define BB 2
#define HH 32
#define SS 16384
#define DD 64
#define NHEADS (BB*HH)
#define SPLIT 16
#define CHUNK (SS/SPLIT)   /* 1024 s-rows per phase1 CTA */
#define NIT (CHUNK/64)     /* 16 staging iterations */

/* phase2 config */
#define TM 64                         /* s-rows per tile */
#define TILES_PER_HEAD (SS / TM)      /* 256 */
#define TIT 16                        /* tiles per CTA */
#define GRID2 (NHEADS * TILES_PER_HEAD / TIT)  /* 1024 */

/* scratch (no runtime alloc) */
__device__ float g_part[(size_t)NHEADS * SPLIT * 4160];
__device__ float g_norm[(size_t)NHEADS * 64];
__device__ __nv_bfloat16 g_memT_hi[(size_t)NHEADS * 4096];  /* [head][dv*64+dk] */
__device__ __nv_bfloat16 g_memT_lo[(size_t)NHEADS * 4096];

__device__ __forceinline__ float elu1(float x) {
    return x > 0.0f ? x + 1.0f : __expf(x);
}

__device__ __forceinline__ uint32_t smem_u32(const void* p) {
    uint32_t a;
    asm("{ .reg .u64 t; cvta.to.shared.u64 t, %1; cvt.u32.u64 %0, t; }" : "=r"(a) : "l"(p));
    return a;
}
__device__ __forceinline__ void ldsm_x4(uint32_t& r0, uint32_t& r1, uint32_t& r2,
                                        uint32_t& r3, uint32_t addr) {
    asm volatile("ldmatrix.sync.aligned.m8n8.x4.shared.b16 {%0,%1,%2,%3}, [%4];"
                 : "=r"(r0), "=r"(r1), "=r"(r2), "=r"(r3) : "r"(addr));
}
__device__ __forceinline__ void ldsm_x4_t(uint32_t& r0, uint32_t& r1, uint32_t& r2,
                                          uint32_t& r3, uint32_t addr) {
    asm volatile("ldmatrix.sync.aligned.m8n8.x4.trans.shared.b16 {%0,%1,%2,%3}, [%4];"
                 : "=r"(r0), "=r"(r1), "=r"(r2), "=r"(r3) : "r"(addr));
}
__device__ __forceinline__ void mma_bf16(float* d, const uint32_t* a,
                                         uint32_t b0, uint32_t b1) {
    asm volatile(
        "mma.sync.aligned.m16n8k16.row.col.f32.bf16.bf16.f32 "
        "{%0,%1,%2,%3}, {%4,%5,%6,%7}, {%8,%9}, {%0,%1,%2,%3};"
        : "+f"(d[0]), "+f"(d[1]), "+f"(d[2]), "+f"(d[3])
        : "r"(a[0]), "r"(a[1]), "r"(a[2]), "r"(a[3]), "r"(b0), "r"(b1));
}

/* swizzled byte offset: 128B rows, 16B units XOR'ed by row&7 */
#define ASWZ(row, unit) (((uint32_t)(row) << 7) + ((((unit) ^ ((row) & 7)) & 7) << 4))

__device__ __forceinline__ uint32_t pack_bf16x2(float lo_val, float hi_val) {
    uint32_t r;
    asm("cvt.rn.bf16x2.f32 %0, %1, %2;" : "=r"(r) : "f"(hi_val), "f"(lo_val));
    return r;
}
__device__ __forceinline__ void split_store(char* hi, char* lo, float4 v,
                                            uint32_t off) {
    uint32_t h0 = pack_bf16x2(v.x, v.y);
    uint32_t h1 = pack_bf16x2(v.z, v.w);
    float hx = __uint_as_float(h0 << 16);
    float hy = __uint_as_float(h0 & 0xffff0000u);
    float hz = __uint_as_float(h1 << 16);
    float hw = __uint_as_float(h1 & 0xffff0000u);
    uint32_t l0 = pack_bf16x2(v.x - hx, v.y - hy);
    uint32_t l1 = pack_bf16x2(v.z - hz, v.w - hw);
    *(uint2*)(hi + off) = make_uint2(h0, h1);
    *(uint2*)(lo + off) = make_uint2(l0, l1);
}

/* ====== Phase 1: M = kf^T @ v, reg prefetch + double-buffered tiles, 1 sync/iter ====== */
/* dyn smem: buf b at b*32768: KH | KL | VH | VL (8K each); nrm at 65536 */
#define P1_NRM   65536
#define P1_TOTAL (65536 + 4096)

__global__ void __launch_bounds__(256, 2)
phase1_mma(const float* __restrict__ kk, const float* __restrict__ vv) {
    extern __shared__ __align__(128) char dyn[];

    const int bx    = blockIdx.x;
    const int head  = bx / SPLIT;
    const int chunk = bx % SPLIT;
    const int tid   = threadIdx.x;
    const int wid   = tid >> 5;
    const int lane  = tid & 31;
    const int mi    = wid >> 1;       /* dk m-tile 0..3 */
    const int nh    = wid & 1;        /* dv half 0..1 */

    const uint32_t sb = smem_u32(dyn);

    uint32_t soff[4];
    #pragma unroll
    for (int p = 0; p < 4; ++p) {
        int f = tid + p * 256;
        int c4 = (f & 15) * 4;
        soff[p] = ASWZ(f >> 4, c4 >> 3) + ((c4 >> 2) & 1) * 8;
    }
    const float* kbase = kk + ((size_t)head * SS + (size_t)chunk * CHUNK) * DD
                            + (size_t)((tid & 15) * 4);
    const float* vbase = vv + ((size_t)head * SS + (size_t)chunk * CHUNK) * DD
                            + (size_t)((tid & 15) * 4);
    const int rbase0 = (tid >> 4);     /* my row within the 64-row block (x4) */

    float acc[4][4] = {};
    float nrm[4]    = {};

    /* prologue: load + convert block 0 into buf 0 */
    float4 pk[4], pv[4];
    #pragma unroll
    for (int p = 0; p < 4; ++p) {
        int r = rbase0 + p * 16;
        pk[p] = *(const float4*)(kbase + (size_t)r * DD);
        pv[p] = *(const float4*)(vbase + (size_t)r * DD);
    }
    #pragma unroll
    for (int p = 0; p < 4; ++p) {
        float4 kf = pk[p];
        kf.x = elu1(kf.x); kf.y = elu1(kf.y); kf.z = elu1(kf.z); kf.w = elu1(kf.w);
        nrm[0] += kf.x; nrm[1] += kf.y; nrm[2] += kf.z; nrm[3] += kf.w;
        split_store(dyn + 0,     dyn + 8192,  kf,    soff[p]);
        split_store(dyn + 16384, dyn + 24576, pv[p], soff[p]);
    }
    __syncthreads();

    for (int it = 0; it < NIT; ++it) {
        /* prefetch block it+1 (LDGs overlap mma below) */
        if (it + 1 < NIT) {
            const float* kn = kbase + (size_t)(it + 1) * 64 * DD;
            const float* vn = vbase + (size_t)(it + 1) * 64 * DD;
            #pragma unroll
            for (int p = 0; p < 4; ++p) {
                int r = rbase0 + p * 16;
                pk[p] = *(const float4*)(kn + (size_t)r * DD);
                pv[p] = *(const float4*)(vn + (size_t)r * DD);
            }
        }

        /* mma on buf[it&1] */
        const uint32_t bufb = sb + (uint32_t)(it & 1) * 32768;
        #pragma unroll
        for (int ps = 0; ps < 3; ++ps) {
            const uint32_t ab = bufb + ((ps == 2) ? 8192 : 0);
            const uint32_t bb = bufb + 16384 + ((ps == 1) ? 8192 : 0);
            #pragma unroll
            for (int kt = 0; kt < 4; ++kt) {
                uint32_t a[4];
                {
                    int ar = kt * 16 + (lane & 7) + ((lane >> 4) << 3);
                    int au = mi * 2 + ((lane >> 3) & 1);
                    ldsm_x4_t(a[0], a[1], a[2], a[3], ab + ASWZ(ar, au));
                }
                uint32_t b[4][2];
                #pragma unroll
                for (int np = 0; np < 2; ++np) {
                    int br = kt * 16 + (lane & 7) + (((lane >> 3) & 1) << 3);
                    int bu = nh * 4 + np * 2 + (lane >> 4);
                    uint32_t r0, r1, r2, r3;
                    ldsm_x4_t(r0, r1, r2, r3, bb + ASWZ(br, bu));
                    b[np*2+0][0] = r0; b[np*2+0][1] = r1;
                    b[np*2+1][0] = r2; b[np*2+1][1] = r3;
                }
                #pragma unroll
                for (int nt = 0; nt < 4; ++nt)
                    mma_bf16(acc[nt], a, b[nt][0], b[nt][1]);
            }
        }

        /* convert block it+1 into buf[(it+1)&1] (stalls covered by other warps' mma) */
        if (it + 1 < NIT) {
            char* nb = dyn + ((it + 1) & 1) * 32768;
            #pragma unroll
            for (int p = 0; p < 4; ++p) {
                float4 kf = pk[p];
                kf.x = elu1(kf.x); kf.y = elu1(kf.y); kf.z = elu1(kf.z); kf.w = elu1(kf.w);
                nrm[0] += kf.x; nrm[1] += kf.y; nrm[2] += kf.z; nrm[3] += kf.w;
                split_store(nb + 0,     nb + 8192,  kf,    soff[p]);
                split_store(nb + 16384, nb + 24576, pv[p], soff[p]);
            }
        }
        __syncthreads();
    }

    /* write M partial */
    float* outp = g_part + (size_t)bx * 4160;
    {
        int r_lo = mi * 16 + (lane >> 2);
        int r_hi = r_lo + 8;
        int c0   = nh * 32 + (lane & 3) * 2;
        #pragma unroll
        for (int nt = 0; nt < 4; ++nt) {
            *(float2*)&outp[r_lo * 64 + nt * 8 + c0] = make_float2(acc[nt][0], acc[nt][1]);
            *(float2*)&outp[r_hi * 64 + nt * 8 + c0] = make_float2(acc[nt][2], acc[nt][3]);
        }
    }
    /* norm: deterministic cross-thread reduction */
    float* snrm = (float*)(dyn + P1_NRM);
    snrm[tid*4+0] = nrm[0]; snrm[tid*4+1] = nrm[1];
    snrm[tid*4+2] = nrm[2]; snrm[tid*4+3] = nrm[3];
    __syncthreads();
    if (tid < 16) {
        float s0 = 0.f, s1 = 0.f, s2 = 0.f, s3 = 0.f;
        #pragma unroll
        for (int g = 0; g < 16; ++g) {
            s0 += snrm[(tid + 16*g)*4+0]; s1 += snrm[(tid + 16*g)*4+1];
            s2 += snrm[(tid + 16*g)*4+2]; s3 += snrm[(tid + 16*g)*4+3];
        }
        *(float4*)&outp[4096 + tid * 4] = make_float4(s0, s1, s2, s3);
    }
}

/* ------- Reduce: sum SPLIT partials; emit transposed bf16 hi/lo + fp32 norm ------- */
__global__ void __launch_bounds__(512) reduce_k() {
    const int head = blockIdx.x;
    for (int e = threadIdx.x; e < 4160; e += 512) {
        float s = 0.f;
        #pragma unroll
        for (int c = 0; c < SPLIT; ++c)
            s += g_part[((size_t)head * SPLIT + c) * 4160 + e];
        if (e < 4096) {
            int dk = e >> 6, dv = e & 63;
            __nv_bfloat16 h = __float2bfloat16(s);
            __nv_bfloat16 l = __float2bfloat16(s - __bfloat162float(h));
            g_memT_hi[(size_t)head * 4096 + dv * 64 + dk] = h;
            g_memT_lo[(size_t)head * 4096 + dv * 64 + dk] = l;
        } else {
            g_norm[(size_t)head * 64 + (e - 4096)] = s;
        }
    }
}

/* ====== Phase 2: Out = Qf @ M^T, double-buffered A/sden, 1 sync/iter ====== */
/* dyn smem: A buf b at b*16384 (AH|AL 8K each); BH 32768; BL 40960; sden 49152 */
#define P2_BH   32768
#define P2_BL   40960
#define P2_DEN  49152                 /* float[2][64] */
#define P2_TOTAL (49152 + 512)

__global__ void __launch_bounds__(256, 2)
phase2_mma(const float* __restrict__ q, float* __restrict__ outg) {
    extern __shared__ __align__(128) char dyn[];

    const int tid  = threadIdx.x;
    const int wid  = tid >> 5;
    const int lane = tid & 31;
    const int mi   = wid >> 1;        /* m-tile 0..3 */
    const int nh   = wid & 1;         /* n-half 0..1 */

    const uint32_t sb = smem_u32(dyn);
    float* sden = (float*)(dyn + P2_DEN);

    const int t0   = blockIdx.x * TIT;
    const int head = t0 / TILES_PER_HEAD;

    /* ---- per-CTA: memory matrix (bf16 hi/lo, swizzled) ---- */
    {
        const __nv_bfloat16* bh = g_memT_hi + (size_t)head * 4096;
        const __nv_bfloat16* bl = g_memT_lo + (size_t)head * 4096;
        #pragma unroll
        for (int p = 0; p < 2; ++p) {
            int f = tid + p * 256;
            int r = f >> 3;
            int u = f & 7;
            uint32_t off = ASWZ(r, u);
            *(uint4*)(dyn + P2_BH + off) = *(const uint4*)(bh + r * 64 + u * 8);
            *(uint4*)(dyn + P2_BL + off) = *(const uint4*)(bl + r * 64 + u * 8);
        }
    }

    int srow[4]; uint32_t soff[4];
    #pragma unroll
    for (int p = 0; p < 4; ++p) {
        int f = tid + p * 256;
        srow[p] = f >> 4;
        int c4 = (f & 15) * 4;
        soff[p] = ASWZ(srow[p], c4 >> 3) + ((c4 >> 2) & 1) * 8;
    }
    const float4 mynrm = *(const float4*)(g_norm + (size_t)head * 64 + (tid & 15) * 4);
    const float* qcol = q + ((size_t)head * SS) * DD + (size_t)((tid & 15) * 4);

    /* prologue: load + convert tile 0 into A buf 0 / sden 0 */
    float4 pq[4];
    {
        const int s0 = (t0 % TILES_PER_HEAD) * TM;
        #pragma unroll
        for (int p = 0; p < 4; ++p)
            pq[p] = *(const float4*)(qcol + (size_t)(s0 + srow[p]) * DD);
        #pragma unroll
        for (int p = 0; p < 4; ++p) {
            float4 v = pq[p];
            v.x = elu1(v.x); v.y = elu1(v.y); v.z = elu1(v.z); v.w = elu1(v.w);
            split_store(dyn + 0, dyn + 8192, v, soff[p]);
            float dp = v.x * mynrm.x + v.y * mynrm.y + v.z * mynrm.z + v.w * mynrm.w;
            dp += __shfl_xor_sync(0xffffffffu, dp, 1);
            dp += __shfl_xor_sync(0xffffffffu, dp, 2);
            dp += __shfl_xor_sync(0xffffffffu, dp, 4);
            dp += __shfl_xor_sync(0xffffffffu, dp, 8);
            if ((lane & 15) == 0) sden[srow[p]] = dp;
        }
    }
    __syncthreads();

    for (int it = 0; it < TIT; ++it) {
        const int s0 = ((t0 + it) % TILES_PER_HEAD) * TM;

        /* prefetch tile it+1 (overlaps mma + epilogue) */
        if (it + 1 < TIT) {
            const int s1 = ((t0 + it + 1) % TILES_PER_HEAD) * TM;
            #pragma unroll
            for (int p = 0; p < 4; ++p)
                pq[p] = *(const float4*)(qcol + (size_t)(s1 + srow[p]) * DD);
        }

        /* mma on A buf[it&1] */
        float acc[4][4];
        #pragma unroll
        for (int nt = 0; nt < 4; ++nt)
            #pragma unroll
            for (int e = 0; e < 4; ++e) acc[nt][e] = 0.f;

        const uint32_t abuf = sb + (uint32_t)(it & 1) * 16384;
        #pragma unroll
        for (int ps = 0; ps < 3; ++ps) {
            const uint32_t abase = abuf + ((ps == 2) ? 8192 : 0);
            const uint32_t bbase = sb + P2_BH + ((ps == 1) ? 8192 : 0);
            #pragma unroll
            for (int kt = 0; kt < 4; ++kt) {
                uint32_t a[4];
                {
                    int ar = mi * 16 + (lane & 15);
                    ldsm_x4(a[0], a[1], a[2], a[3],
                            abase + ASWZ(ar, kt * 2 + (lane >> 4)));
                }
                uint32_t b[4][2];
                #pragma unroll
                for (int np = 0; np < 2; ++np) {
                    int br = nh * 32 + np * 16 + (lane & 7) + ((lane >> 4) << 3);
                    uint32_t r0, r1, r2, r3;
                    ldsm_x4(r0, r1, r2, r3,
                            bbase + ASWZ(br, kt * 2 + ((lane >> 3) & 1)));
                    b[np*2+0][0] = r0; b[np*2+0][1] = r1;
                    b[np*2+1][0] = r2; b[np*2+1][1] = r3;
                }
                #pragma unroll
                for (int nt = 0; nt < 4; ++nt)
                    mma_bf16(acc[nt], a, b[nt][0], b[nt][1]);
            }
        }

        /* epilogue: divide by sden[it&1], store */
        {
            const float* dcur = sden + (it & 1) * 64;
            int r_lo = mi * 16 + (lane >> 2);
            int r_hi = r_lo + 8;
            float inv_lo = 1.0f / dcur[r_lo];
            float inv_hi = 1.0f / dcur[r_hi];
            float* obase = outg + ((size_t)head * SS + (size_t)s0) * DD;
            int c0 = nh * 32 + (lane & 3) * 2;
            #pragma unroll
            for (int nt = 0; nt < 4; ++nt) {
                *(float2*)(obase + (size_t)r_lo * DD + nt * 8 + c0) =
                    make_float2(acc[nt][0] * inv_lo, acc[nt][1] * inv_lo);
                *(float2*)(obase + (size_t)r_hi * DD + nt * 8 + c0) =
                    make_float2(acc[nt][2] * inv_hi, acc[nt][3] * inv_hi);
            }
        }

        /* convert tile it+1 into A buf[(it+1)&1] / sden[(it+1)&1] */
        if (it + 1 < TIT) {
            char* ab = dyn + ((it + 1) & 1) * 16384;
            float* dnx = sden + ((it + 1) & 1) * 64;
            #pragma unroll
            for (int p = 0; p < 4; ++p) {
                float4 v = pq[p];
                v.x = elu1(v.x); v.y = elu1(v.y); v.z = elu1(v.z); v.w = elu1(v.w);
                split_store(ab, ab + 8192, v, soff[p]);
                float dp = v.x * mynrm.x + v.y * mynrm.y + v.z * mynrm.z + v.w * mynrm.w;
                dp += __shfl_xor_sync(0xffffffffu, dp, 1);
                dp += __shfl_xor_sync(0xffffffffu, dp, 2);
                dp += __shfl_xor_sync(0xffffffffu, dp, 4);
                dp += __shfl_xor_sync(0xffffffffu, dp, 8);
                if ((lane & 15) == 0) dnx[srow[p]] = dp;
            }
        }
        __syncthreads();
    }
}

extern "C" void kernel_launch(void* const* d_in, const int* in_sizes, int n_in,
                              void* d_out, int out_size) {
    const float* q = (const float*)d_in[0];
    const float* k = (const float*)d_in[1];
    const float* v = (const float*)d_in[2];
    float* out = (float*)d_out;

    cudaFuncSetAttribute(phase1_mma, cudaFuncAttributeMaxDynamicSharedMemorySize,
                         P1_TOTAL);
    cudaFuncSetAttribute(phase2_mma, cudaFuncAttributeMaxDynamicSharedMemorySize,
                         P2_TOTAL);

    phase1_mma<<<NHEADS * SPLIT, 256, P1_TOTAL>>>(k, v);
    reduce_k<<<NHEADS, 512>>>();
    phase2_mma<<<GRID2, 256, P2_TOTAL>>>(q, out);
}

// round 13
// speedup vs baseline: 1.1192x; 1.0001x over previous
#include <cuda_runtime.h>
#include <cuda_bf16.h>
#include <cstdint>

#define BB 2
#define HH 32
#define SS 16384
#define DD 64
#define NHEADS (BB*HH)
#define SPLIT 32
#define CHUNK (SS/SPLIT)   /* 512 s-rows per phase1 CTA */
#define NIT (CHUNK/64)     /* 8 staging iterations */

/* phase2 config */
#define TM 64                         /* s-rows per tile */
#define TILES_PER_HEAD (SS / TM)      /* 256 */
#define TIT 8                         /* tiles per CTA */
#define GRID2 (NHEADS * TILES_PER_HEAD / TIT)  /* 2048 */

/* scratch (no runtime alloc) */
__device__ float g_part[(size_t)NHEADS * SPLIT * 4160];
__device__ float g_norm[(size_t)NHEADS * 64];
__device__ __nv_bfloat16 g_memT_hi[(size_t)NHEADS * 4096];  /* [head][dv*64+dk] */
__device__ __nv_bfloat16 g_memT_lo[(size_t)NHEADS * 4096];

__device__ __forceinline__ float elu1(float x) {
    return x > 0.0f ? x + 1.0f : __expf(x);
}

__device__ __forceinline__ uint32_t smem_u32(const void* p) {
    uint32_t a;
    asm("{ .reg .u64 t; cvta.to.shared.u64 t, %1; cvt.u32.u64 %0, t; }" : "=r"(a) : "l"(p));
    return a;
}
__device__ __forceinline__ void ldsm_x4(uint32_t& r0, uint32_t& r1, uint32_t& r2,
                                        uint32_t& r3, uint32_t addr) {
    asm volatile("ldmatrix.sync.aligned.m8n8.x4.shared.b16 {%0,%1,%2,%3}, [%4];"
                 : "=r"(r0), "=r"(r1), "=r"(r2), "=r"(r3) : "r"(addr));
}
__device__ __forceinline__ void ldsm_x4_t(uint32_t& r0, uint32_t& r1, uint32_t& r2,
                                          uint32_t& r3, uint32_t addr) {
    asm volatile("ldmatrix.sync.aligned.m8n8.x4.trans.shared.b16 {%0,%1,%2,%3}, [%4];"
                 : "=r"(r0), "=r"(r1), "=r"(r2), "=r"(r3) : "r"(addr));
}
__device__ __forceinline__ void mma_bf16(float* d, const uint32_t* a,
                                         uint32_t b0, uint32_t b1) {
    asm volatile(
        "mma.sync.aligned.m16n8k16.row.col.f32.bf16.bf16.f32 "
        "{%0,%1,%2,%3}, {%4,%5,%6,%7}, {%8,%9}, {%0,%1,%2,%3};"
        : "+f"(d[0]), "+f"(d[1]), "+f"(d[2]), "+f"(d[3])
        : "r"(a[0]), "r"(a[1]), "r"(a[2]), "r"(a[3]), "r"(b0), "r"(b1));
}

/* swizzled byte offset: 128B rows, 16B units XOR'ed by row&7 */
#define ASWZ(row, unit) (((uint32_t)(row) << 7) + ((((unit) ^ ((row) & 7)) & 7) << 4))

__device__ __forceinline__ uint32_t pack_bf16x2(float lo_val, float hi_val) {
    uint32_t r;
    asm("cvt.rn.bf16x2.f32 %0, %1, %2;" : "=r"(r) : "f"(hi_val), "f"(lo_val));
    return r;
}
__device__ __forceinline__ void split_store(char* hi, char* lo, float4 v,
                                            uint32_t off) {
    uint32_t h0 = pack_bf16x2(v.x, v.y);
    uint32_t h1 = pack_bf16x2(v.z, v.w);
    float hx = __uint_as_float(h0 << 16);
    float hy = __uint_as_float(h0 & 0xffff0000u);
    float hz = __uint_as_float(h1 << 16);
    float hw = __uint_as_float(h1 & 0xffff0000u);
    uint32_t l0 = pack_bf16x2(v.x - hx, v.y - hy);
    uint32_t l1 = pack_bf16x2(v.z - hz, v.w - hw);
    *(uint2*)(hi + off) = make_uint2(h0, h1);
    *(uint2*)(lo + off) = make_uint2(l0, l1);
}

/* ============ Phase 1: M = kf^T @ v via mma.sync, pipelined staging ============ */
__global__ void __launch_bounds__(256, 2)
phase1_mma(const float* __restrict__ kk, const float* __restrict__ vv) {
    __shared__ __align__(128) char sKH[8192];
    __shared__ __align__(128) char sKL[8192];
    __shared__ __align__(128) char sVH[8192];
    __shared__ __align__(128) char sVL[8192];
    __shared__ float s_nrm[256][4];

    const int bx    = blockIdx.x;
    const int head  = bx / SPLIT;
    const int chunk = bx % SPLIT;
    const int tid   = threadIdx.x;
    const int wid   = tid >> 5;
    const int lane  = tid & 31;
    const int mi    = wid >> 1;       /* dk m-tile 0..3 */
    const int nh    = wid & 1;        /* dv half 0..1 */

    const uint32_t aKH = smem_u32(sKH), aKL = smem_u32(sKL);
    const uint32_t aVH = smem_u32(sVH), aVL = smem_u32(sVL);

    int srow[4]; uint32_t soff[4];
    #pragma unroll
    for (int p = 0; p < 4; ++p) {
        int f = tid + p * 256;
        srow[p] = f >> 4;
        int c4 = (f & 15) * 4;
        soff[p] = ASWZ(srow[p], c4 >> 3) + ((c4 >> 2) & 1) * 8;
    }
    const float* kbase = kk + ((size_t)head * SS + (size_t)chunk * CHUNK) * DD
                            + (size_t)((tid & 15) * 4);
    const float* vbase = vv + ((size_t)head * SS + (size_t)chunk * CHUNK) * DD
                            + (size_t)((tid & 15) * 4);

    float acc[4][4] = {};
    float nrm[4]    = {};

    float4 pk[4], pv[4];
    #pragma unroll
    for (int p = 0; p < 4; ++p) {
        pk[p] = *(const float4*)(kbase + (size_t)srow[p] * DD);
        pv[p] = *(const float4*)(vbase + (size_t)srow[p] * DD);
    }

    for (int it = 0; it < NIT; ++it) {
        __syncthreads();
        #pragma unroll
        for (int p = 0; p < 4; ++p) {
            float4 kf = pk[p];
            kf.x = elu1(kf.x); kf.y = elu1(kf.y); kf.z = elu1(kf.z); kf.w = elu1(kf.w);
            nrm[0] += kf.x; nrm[1] += kf.y; nrm[2] += kf.z; nrm[3] += kf.w;
            split_store(sKH, sKL, kf, soff[p]);
            split_store(sVH, sVL, pv[p], soff[p]);
        }
        __syncthreads();

        /* prefetch next block — LDGs in flight during the mma section */
        if (it + 1 < NIT) {
            const float* kn = kbase + (size_t)(it + 1) * 64 * DD;
            const float* vn = vbase + (size_t)(it + 1) * 64 * DD;
            #pragma unroll
            for (int p = 0; p < 4; ++p) {
                pk[p] = *(const float4*)(kn + (size_t)srow[p] * DD);
                pv[p] = *(const float4*)(vn + (size_t)srow[p] * DD);
            }
        }

        #pragma unroll
        for (int ps = 0; ps < 3; ++ps) {
            const uint32_t ab = (ps == 2) ? aKL : aKH;
            const uint32_t bb = (ps == 1) ? aVL : aVH;
            #pragma unroll
            for (int kt = 0; kt < 4; ++kt) {
                uint32_t a[4];
                {
                    int ar = kt * 16 + (lane & 7) + ((lane >> 4) << 3);
                    int au = mi * 2 + ((lane >> 3) & 1);
                    ldsm_x4_t(a[0], a[1], a[2], a[3], ab + ASWZ(ar, au));
                }
                uint32_t b[4][2];
                #pragma unroll
                for (int np = 0; np < 2; ++np) {
                    int br = kt * 16 + (lane & 7) + (((lane >> 3) & 1) << 3);
                    int bu = nh * 4 + np * 2 + (lane >> 4);
                    uint32_t r0, r1, r2, r3;
                    ldsm_x4_t(r0, r1, r2, r3, bb + ASWZ(br, bu));
                    b[np*2+0][0] = r0; b[np*2+0][1] = r1;
                    b[np*2+1][0] = r2; b[np*2+1][1] = r3;
                }
                #pragma unroll
                for (int nt = 0; nt < 4; ++nt)
                    mma_bf16(acc[nt], a, b[nt][0], b[nt][1]);
            }
        }
    }

    /* write M partial */
    float* outp = g_part + (size_t)bx * 4160;
    {
        int r_lo = mi * 16 + (lane >> 2);
        int r_hi = r_lo + 8;
        int c0   = nh * 32 + (lane & 3) * 2;
        #pragma unroll
        for (int nt = 0; nt < 4; ++nt) {
            *(float2*)&outp[r_lo * 64 + nt * 8 + c0] = make_float2(acc[nt][0], acc[nt][1]);
            *(float2*)&outp[r_hi * 64 + nt * 8 + c0] = make_float2(acc[nt][2], acc[nt][3]);
        }
    }
    /* norm: deterministic cross-thread reduction */
    s_nrm[tid][0] = nrm[0]; s_nrm[tid][1] = nrm[1];
    s_nrm[tid][2] = nrm[2]; s_nrm[tid][3] = nrm[3];
    __syncthreads();
    if (tid < 16) {
        float s0 = 0.f, s1 = 0.f, s2 = 0.f, s3 = 0.f;
        #pragma unroll
        for (int g = 0; g < 16; ++g) {
            s0 += s_nrm[tid + 16*g][0]; s1 += s_nrm[tid + 16*g][1];
            s2 += s_nrm[tid + 16*g][2]; s3 += s_nrm[tid + 16*g][3];
        }
        *(float4*)&outp[4096 + tid * 4] = make_float4(s0, s1, s2, s3);
    }
}

/* ------- Reduce: sum SPLIT partials; emit transposed bf16 hi/lo + fp32 norm ------- */
__global__ void __launch_bounds__(512) reduce_k() {
    const int head = blockIdx.x;
    for (int e = threadIdx.x; e < 4160; e += 512) {
        float s = 0.f;
        #pragma unroll 8
        for (int c = 0; c < SPLIT; ++c)
            s += g_part[((size_t)head * SPLIT + c) * 4160 + e];
        if (e < 4096) {
            int dk = e >> 6, dv = e & 63;
            __nv_bfloat16 h = __float2bfloat16(s);
            __nv_bfloat16 l = __float2bfloat16(s - __bfloat162float(h));
            g_memT_hi[(size_t)head * 4096 + dv * 64 + dk] = h;
            g_memT_lo[(size_t)head * 4096 + dv * 64 + dk] = l;
        } else {
            g_norm[(size_t)head * 64 + (e - 4096)] = s;
        }
    }
}

/* ============ Phase 2: Out = Qf @ M^T via mma.sync, den fused into staging ============ */
__global__ void __launch_bounds__(256, 2)
phase2_mma(const float* __restrict__ q, float* __restrict__ outg) {
    __shared__ __align__(128) char sAH[8192];
    __shared__ __align__(128) char sAL[8192];
    __shared__ __align__(128) char sBH[8192];
    __shared__ __align__(128) char sBL[8192];
    __shared__ float sden[64];

    const int tid  = threadIdx.x;
    const int wid  = tid >> 5;
    const int lane = tid & 31;
    const int mi   = wid >> 1;        /* m-tile 0..3 */
    const int nh   = wid & 1;         /* n-half 0..1 */

    const uint32_t aAH = smem_u32(sAH), aAL = smem_u32(sAL);
    const uint32_t aBH = smem_u32(sBH), aBL = smem_u32(sBL);

    const int t0   = blockIdx.x * TIT;
    const int head = t0 / TILES_PER_HEAD;

    /* ---- per-CTA: memory matrix (bf16 hi/lo, swizzled) ---- */
    {
        const __nv_bfloat16* bh = g_memT_hi + (size_t)head * 4096;
        const __nv_bfloat16* bl = g_memT_lo + (size_t)head * 4096;
        #pragma unroll
        for (int p = 0; p < 2; ++p) {
            int f = tid + p * 256;
            int r = f >> 3;
            int u = f & 7;
            uint32_t off = ASWZ(r, u);
            *(uint4*)(sBH + off) = *(const uint4*)(bh + r * 64 + u * 8);
            *(uint4*)(sBL + off) = *(const uint4*)(bl + r * 64 + u * 8);
        }
    }

    /* per-thread staging slots; this thread's fixed 4 columns */
    int srow[4]; uint32_t soff[4];
    #pragma unroll
    for (int p = 0; p < 4; ++p) {
        int f = tid + p * 256;
        srow[p] = f >> 4;
        int c4 = (f & 15) * 4;
        soff[p] = ASWZ(srow[p], c4 >> 3) + ((c4 >> 2) & 1) * 8;
    }
    const float4 mynrm = *(const float4*)(g_norm + (size_t)head * 64 + (tid & 15) * 4);
    const float* qcol = q + ((size_t)head * SS) * DD + (size_t)((tid & 15) * 4);

    /* prefetch tile 0 */
    float4 pq[4];
    {
        const int s0 = (t0 % TILES_PER_HEAD) * TM;
        #pragma unroll
        for (int p = 0; p < 4; ++p)
            pq[p] = *(const float4*)(qcol + (size_t)(s0 + srow[p]) * DD);
    }

    for (int it = 0; it < TIT; ++it) {
        const int s0 = ((t0 + it) % TILES_PER_HEAD) * TM;

        __syncthreads();   /* prior tile done reading A/sden */

        /* ---- stage A + fused denominator (fp32, deterministic shfl tree) ---- */
        #pragma unroll
        for (int p = 0; p < 4; ++p) {
            float4 v = pq[p];
            v.x = elu1(v.x); v.y = elu1(v.y); v.z = elu1(v.z); v.w = elu1(v.w);
            split_store(sAH, sAL, v, soff[p]);
            float dp = v.x * mynrm.x + v.y * mynrm.y + v.z * mynrm.z + v.w * mynrm.w;
            dp += __shfl_xor_sync(0xffffffffu, dp, 1);
            dp += __shfl_xor_sync(0xffffffffu, dp, 2);
            dp += __shfl_xor_sync(0xffffffffu, dp, 4);
            dp += __shfl_xor_sync(0xffffffffu, dp, 8);
            if ((lane & 15) == 0) sden[srow[p]] = dp;
        }
        __syncthreads();

        /* prefetch next tile — LDGs overlap mma + epilogue */
        if (it + 1 < TIT) {
            const int s1 = ((t0 + it + 1) % TILES_PER_HEAD) * TM;
            #pragma unroll
            for (int p = 0; p < 4; ++p)
                pq[p] = *(const float4*)(qcol + (size_t)(s1 + srow[p]) * DD);
        }

        /* ---- 3-pass bf16 mma: hh + hl + lh ---- */
        float acc[4][4];
        #pragma unroll
        for (int nt = 0; nt < 4; ++nt)
            #pragma unroll
            for (int e = 0; e < 4; ++e) acc[nt][e] = 0.f;

        #pragma unroll
        for (int ps = 0; ps < 3; ++ps) {
            const uint32_t abase = (ps == 2) ? aAL : aAH;
            const uint32_t bbase = (ps == 1) ? aBL : aBH;
            #pragma unroll
            for (int kt = 0; kt < 4; ++kt) {
                uint32_t a[4];
                {
                    int ar = mi * 16 + (lane & 15);
                    ldsm_x4(a[0], a[1], a[2], a[3],
                            abase + ASWZ(ar, kt * 2 + (lane >> 4)));
                }
                uint32_t b[4][2];
                #pragma unroll
                for (int np = 0; np < 2; ++np) {
                    int br = nh * 32 + np * 16 + (lane & 7) + ((lane >> 4) << 3);
                    uint32_t r0, r1, r2, r3;
                    ldsm_x4(r0, r1, r2, r3,
                            bbase + ASWZ(br, kt * 2 + ((lane >> 3) & 1)));
                    b[np*2+0][0] = r0; b[np*2+0][1] = r1;
                    b[np*2+1][0] = r2; b[np*2+1][1] = r3;
                }
                #pragma unroll
                for (int nt = 0; nt < 4; ++nt)
                    mma_bf16(acc[nt], a, b[nt][0], b[nt][1]);
            }
        }

        /* ---- epilogue: divide, store (sden valid since post-staging sync) ---- */
        int r_lo = mi * 16 + (lane >> 2);
        int r_hi = r_lo + 8;
        float inv_lo = 1.0f / sden[r_lo];
        float inv_hi = 1.0f / sden[r_hi];
        float* obase = outg + ((size_t)head * SS + (size_t)s0) * DD;
        int c0 = nh * 32 + (lane & 3) * 2;
        #pragma unroll
        for (int nt = 0; nt < 4; ++nt) {
            *(float2*)(obase + (size_t)r_lo * DD + nt * 8 + c0) =
                make_float2(acc[nt][0] * inv_lo, acc[nt][1] * inv_lo);
            *(float2*)(obase + (size_t)r_hi * DD + nt * 8 + c0) =
                make_float2(acc[nt][2] * inv_hi, acc[nt][3] * inv_hi);
        }
    }
}

extern "C" void kernel_launch(void* const* d_in, const int* in_sizes, int n_in,
                              void* d_out, int out_size) {
    const float* q = (const float*)d_in[0];
    const float* k = (const float*)d_in[1];
    const float* v = (const float*)d_in[2];
    float* out = (float*)d_out;

    phase1_mma<<<NHEADS * SPLIT, 256>>>(k, v);
    reduce_k<<<NHEADS, 512>>>();
    phase2_mma<<<GRID2, 256>>>(q, out);
}

// round 14
// speedup vs baseline: 1.1545x; 1.0316x over previous
#include <cuda_runtime.h>
#include <cuda_bf16.h>
#include <cstdint>

#define BB 2
#define HH 32
#define SS 16384
#define DD 64
#define NHEADS (BB*HH)
#define SPLIT 32
#define CHUNK (SS/SPLIT)   /* 512 s-rows per phase1 CTA */
#define NIT (CHUNK/64)     /* 8 staging iterations */

/* phase2 config */
#define TM 64                         /* s-rows per tile */
#define TILES_PER_HEAD (SS / TM)      /* 256 */
#define TIT 16                        /* tiles per CTA */
#define GRID2 (NHEADS * TILES_PER_HEAD / TIT)  /* 1024 */

/* scratch (no runtime alloc) */
__device__ float g_part[(size_t)NHEADS * SPLIT * 4160];
__device__ float g_norm[(size_t)NHEADS * 64];
__device__ __nv_bfloat16 g_memT_hi[(size_t)NHEADS * 4096];  /* [head][dv*64+dk] */
__device__ __nv_bfloat16 g_memT_lo[(size_t)NHEADS * 4096];

__device__ __forceinline__ float elu1(float x) {
    return x > 0.0f ? x + 1.0f : __expf(x);
}

__device__ __forceinline__ uint32_t smem_u32(const void* p) {
    uint32_t a;
    asm("{ .reg .u64 t; cvta.to.shared.u64 t, %1; cvt.u32.u64 %0, t; }" : "=r"(a) : "l"(p));
    return a;
}
__device__ __forceinline__ void ldsm_x4(uint32_t& r0, uint32_t& r1, uint32_t& r2,
                                        uint32_t& r3, uint32_t addr) {
    asm volatile("ldmatrix.sync.aligned.m8n8.x4.shared.b16 {%0,%1,%2,%3}, [%4];"
                 : "=r"(r0), "=r"(r1), "=r"(r2), "=r"(r3) : "r"(addr));
}
__device__ __forceinline__ void ldsm_x4_t(uint32_t& r0, uint32_t& r1, uint32_t& r2,
                                          uint32_t& r3, uint32_t addr) {
    asm volatile("ldmatrix.sync.aligned.m8n8.x4.trans.shared.b16 {%0,%1,%2,%3}, [%4];"
                 : "=r"(r0), "=r"(r1), "=r"(r2), "=r"(r3) : "r"(addr));
}
__device__ __forceinline__ void mma_bf16(float* d, const uint32_t* a,
                                         uint32_t b0, uint32_t b1) {
    asm volatile(
        "mma.sync.aligned.m16n8k16.row.col.f32.bf16.bf16.f32 "
        "{%0,%1,%2,%3}, {%4,%5,%6,%7}, {%8,%9}, {%0,%1,%2,%3};"
        : "+f"(d[0]), "+f"(d[1]), "+f"(d[2]), "+f"(d[3])
        : "r"(a[0]), "r"(a[1]), "r"(a[2]), "r"(a[3]), "r"(b0), "r"(b1));
}

/* swizzled byte offset: 128B rows, 16B units XOR'ed by row&7 */
#define ASWZ(row, unit) (((uint32_t)(row) << 7) + ((((unit) ^ ((row) & 7)) & 7) << 4))

__device__ __forceinline__ uint32_t pack_bf16x2(float lo_val, float hi_val) {
    uint32_t r;
    asm("cvt.rn.bf16x2.f32 %0, %1, %2;" : "=r"(r) : "f"(hi_val), "f"(lo_val));
    return r;
}
__device__ __forceinline__ void split_store(char* hi, char* lo, float4 v,
                                            uint32_t off) {
    uint32_t h0 = pack_bf16x2(v.x, v.y);
    uint32_t h1 = pack_bf16x2(v.z, v.w);
    float hx = __uint_as_float(h0 << 16);
    float hy = __uint_as_float(h0 & 0xffff0000u);
    float hz = __uint_as_float(h1 << 16);
    float hw = __uint_as_float(h1 & 0xffff0000u);
    uint32_t l0 = pack_bf16x2(v.x - hx, v.y - hy);
    uint32_t l1 = pack_bf16x2(v.z - hz, v.w - hw);
    *(uint2*)(hi + off) = make_uint2(h0, h1);
    *(uint2*)(lo + off) = make_uint2(l0, l1);
}

/* ============ Phase 1: M = kf^T @ v via mma.sync, pipelined staging ============ */
__global__ void __launch_bounds__(256, 2)
phase1_mma(const float* __restrict__ kk, const float* __restrict__ vv) {
    __shared__ __align__(128) char sKH[8192];
    __shared__ __align__(128) char sKL[8192];
    __shared__ __align__(128) char sVH[8192];
    __shared__ __align__(128) char sVL[8192];
    __shared__ float s_nrm[256][4];

    const int bx    = blockIdx.x;
    const int head  = bx / SPLIT;
    const int chunk = bx % SPLIT;
    const int tid   = threadIdx.x;
    const int wid   = tid >> 5;
    const int lane  = tid & 31;
    const int mi    = wid >> 1;       /* dk m-tile 0..3 */
    const int nh    = wid & 1;        /* dv half 0..1 */

    const uint32_t aKH = smem_u32(sKH), aKL = smem_u32(sKL);
    const uint32_t aVH = smem_u32(sVH), aVL = smem_u32(sVL);

    int srow[4]; uint32_t soff[4];
    #pragma unroll
    for (int p = 0; p < 4; ++p) {
        int f = tid + p * 256;
        srow[p] = f >> 4;
        int c4 = (f & 15) * 4;
        soff[p] = ASWZ(srow[p], c4 >> 3) + ((c4 >> 2) & 1) * 8;
    }
    const float* kbase = kk + ((size_t)head * SS + (size_t)chunk * CHUNK) * DD
                            + (size_t)((tid & 15) * 4);
    const float* vbase = vv + ((size_t)head * SS + (size_t)chunk * CHUNK) * DD
                            + (size_t)((tid & 15) * 4);

    float acc[4][4] = {};
    float nrm[4]    = {};

    float4 pk[4], pv[4];
    #pragma unroll
    for (int p = 0; p < 4; ++p) {
        pk[p] = __ldcs((const float4*)(kbase + (size_t)srow[p] * DD));
        pv[p] = __ldcs((const float4*)(vbase + (size_t)srow[p] * DD));
    }

    for (int it = 0; it < NIT; ++it) {
        __syncthreads();
        #pragma unroll
        for (int p = 0; p < 4; ++p) {
            float4 kf = pk[p];
            kf.x = elu1(kf.x); kf.y = elu1(kf.y); kf.z = elu1(kf.z); kf.w = elu1(kf.w);
            nrm[0] += kf.x; nrm[1] += kf.y; nrm[2] += kf.z; nrm[3] += kf.w;
            split_store(sKH, sKL, kf, soff[p]);
            split_store(sVH, sVL, pv[p], soff[p]);
        }
        __syncthreads();

        /* prefetch next block — LDGs in flight during the mma section */
        if (it + 1 < NIT) {
            const float* kn = kbase + (size_t)(it + 1) * 64 * DD;
            const float* vn = vbase + (size_t)(it + 1) * 64 * DD;
            #pragma unroll
            for (int p = 0; p < 4; ++p) {
                pk[p] = __ldcs((const float4*)(kn + (size_t)srow[p] * DD));
                pv[p] = __ldcs((const float4*)(vn + (size_t)srow[p] * DD));
            }
        }

        #pragma unroll
        for (int ps = 0; ps < 3; ++ps) {
            const uint32_t ab = (ps == 2) ? aKL : aKH;
            const uint32_t bb = (ps == 1) ? aVL : aVH;
            #pragma unroll
            for (int kt = 0; kt < 4; ++kt) {
                uint32_t a[4];
                {
                    int ar = kt * 16 + (lane & 7) + ((lane >> 4) << 3);
                    int au = mi * 2 + ((lane >> 3) & 1);
                    ldsm_x4_t(a[0], a[1], a[2], a[3], ab + ASWZ(ar, au));
                }
                uint32_t b[4][2];
                #pragma unroll
                for (int np = 0; np < 2; ++np) {
                    int br = kt * 16 + (lane & 7) + (((lane >> 3) & 1) << 3);
                    int bu = nh * 4 + np * 2 + (lane >> 4);
                    uint32_t r0, r1, r2, r3;
                    ldsm_x4_t(r0, r1, r2, r3, bb + ASWZ(br, bu));
                    b[np*2+0][0] = r0; b[np*2+0][1] = r1;
                    b[np*2+1][0] = r2; b[np*2+1][1] = r3;
                }
                #pragma unroll
                for (int nt = 0; nt < 4; ++nt)
                    mma_bf16(acc[nt], a, b[nt][0], b[nt][1]);
            }
        }
    }

    /* write M partial */
    float* outp = g_part + (size_t)bx * 4160;
    {
        int r_lo = mi * 16 + (lane >> 2);
        int r_hi = r_lo + 8;
        int c0   = nh * 32 + (lane & 3) * 2;
        #pragma unroll
        for (int nt = 0; nt < 4; ++nt) {
            *(float2*)&outp[r_lo * 64 + nt * 8 + c0] = make_float2(acc[nt][0], acc[nt][1]);
            *(float2*)&outp[r_hi * 64 + nt * 8 + c0] = make_float2(acc[nt][2], acc[nt][3]);
        }
    }
    /* norm: deterministic cross-thread reduction */
    s_nrm[tid][0] = nrm[0]; s_nrm[tid][1] = nrm[1];
    s_nrm[tid][2] = nrm[2]; s_nrm[tid][3] = nrm[3];
    __syncthreads();
    if (tid < 16) {
        float s0 = 0.f, s1 = 0.f, s2 = 0.f, s3 = 0.f;
        #pragma unroll
        for (int g = 0; g < 16; ++g) {
            s0 += s_nrm[tid + 16*g][0]; s1 += s_nrm[tid + 16*g][1];
            s2 += s_nrm[tid + 16*g][2]; s3 += s_nrm[tid + 16*g][3];
        }
        *(float4*)&outp[4096 + tid * 4] = make_float4(s0, s1, s2, s3);
    }
}

/* ------- Reduce: sum SPLIT partials; emit transposed bf16 hi/lo + fp32 norm ------- */
__global__ void __launch_bounds__(512) reduce_k() {
    const int head = blockIdx.x;
    for (int e = threadIdx.x; e < 4160; e += 512) {
        float s = 0.f;
        #pragma unroll 8
        for (int c = 0; c < SPLIT; ++c)
            s += __ldcs(&g_part[((size_t)head * SPLIT + c) * 4160 + e]);
        if (e < 4096) {
            int dk = e >> 6, dv = e & 63;
            __nv_bfloat16 h = __float2bfloat16(s);
            __nv_bfloat16 l = __float2bfloat16(s - __bfloat162float(h));
            g_memT_hi[(size_t)head * 4096 + dv * 64 + dk] = h;
            g_memT_lo[(size_t)head * 4096 + dv * 64 + dk] = l;
        } else {
            g_norm[(size_t)head * 64 + (e - 4096)] = s;
        }
    }
}

/* ============ Phase 2: Out = Qf @ M^T via mma.sync, den fused into staging ============ */
__global__ void __launch_bounds__(256, 2)
phase2_mma(const float* __restrict__ q, float* __restrict__ outg) {
    __shared__ __align__(128) char sAH[8192];
    __shared__ __align__(128) char sAL[8192];
    __shared__ __align__(128) char sBH[8192];
    __shared__ __align__(128) char sBL[8192];
    __shared__ float sden[64];

    const int tid  = threadIdx.x;
    const int wid  = tid >> 5;
    const int lane = tid & 31;
    const int mi   = wid >> 1;        /* m-tile 0..3 */
    const int nh   = wid & 1;         /* n-half 0..1 */

    const uint32_t aAH = smem_u32(sAH), aAL = smem_u32(sAL);
    const uint32_t aBH = smem_u32(sBH), aBL = smem_u32(sBL);

    const int t0   = blockIdx.x * TIT;
    const int head = t0 / TILES_PER_HEAD;

    /* ---- per-CTA: memory matrix (bf16 hi/lo, swizzled) ---- */
    {
        const __nv_bfloat16* bh = g_memT_hi + (size_t)head * 4096;
        const __nv_bfloat16* bl = g_memT_lo + (size_t)head * 4096;
        #pragma unroll
        for (int p = 0; p < 2; ++p) {
            int f = tid + p * 256;
            int r = f >> 3;
            int u = f & 7;
            uint32_t off = ASWZ(r, u);
            *(uint4*)(sBH + off) = *(const uint4*)(bh + r * 64 + u * 8);
            *(uint4*)(sBL + off) = *(const uint4*)(bl + r * 64 + u * 8);
        }
    }

    /* per-thread staging slots; this thread's fixed 4 columns */
    int srow[4]; uint32_t soff[4];
    #pragma unroll
    for (int p = 0; p < 4; ++p) {
        int f = tid + p * 256;
        srow[p] = f >> 4;
        int c4 = (f & 15) * 4;
        soff[p] = ASWZ(srow[p], c4 >> 3) + ((c4 >> 2) & 1) * 8;
    }
    const float4 mynrm = *(const float4*)(g_norm + (size_t)head * 64 + (tid & 15) * 4);
    const float* qcol = q + ((size_t)head * SS) * DD + (size_t)((tid & 15) * 4);

    /* prefetch tile 0 */
    float4 pq[4];
    {
        const int s0 = (t0 % TILES_PER_HEAD) * TM;
        #pragma unroll
        for (int p = 0; p < 4; ++p)
            pq[p] = __ldcs((const float4*)(qcol + (size_t)(s0 + srow[p]) * DD));
    }

    for (int it = 0; it < TIT; ++it) {
        const int s0 = ((t0 + it) % TILES_PER_HEAD) * TM;

        __syncthreads();   /* prior tile done reading A/sden */

        /* ---- stage A + fused denominator (fp32, deterministic shfl tree) ---- */
        #pragma unroll
        for (int p = 0; p < 4; ++p) {
            float4 v = pq[p];
            v.x = elu1(v.x); v.y = elu1(v.y); v.z = elu1(v.z); v.w = elu1(v.w);
            split_store(sAH, sAL, v, soff[p]);
            float dp = v.x * mynrm.x + v.y * mynrm.y + v.z * mynrm.z + v.w * mynrm.w;
            dp += __shfl_xor_sync(0xffffffffu, dp, 1);
            dp += __shfl_xor_sync(0xffffffffu, dp, 2);
            dp += __shfl_xor_sync(0xffffffffu, dp, 4);
            dp += __shfl_xor_sync(0xffffffffu, dp, 8);
            if ((lane & 15) == 0) sden[srow[p]] = dp;
        }
        __syncthreads();

        /* prefetch next tile — LDGs overlap mma + epilogue */
        if (it + 1 < TIT) {
            const int s1 = ((t0 + it + 1) % TILES_PER_HEAD) * TM;
            #pragma unroll
            for (int p = 0; p < 4; ++p)
                pq[p] = __ldcs((const float4*)(qcol + (size_t)(s1 + srow[p]) * DD));
        }

        /* ---- 3-pass bf16 mma: hh + hl + lh ---- */
        float acc[4][4];
        #pragma unroll
        for (int nt = 0; nt < 4; ++nt)
            #pragma unroll
            for (int e = 0; e < 4; ++e) acc[nt][e] = 0.f;

        #pragma unroll
        for (int ps = 0; ps < 3; ++ps) {
            const uint32_t abase = (ps == 2) ? aAL : aAH;
            const uint32_t bbase = (ps == 1) ? aBL : aBH;
            #pragma unroll
            for (int kt = 0; kt < 4; ++kt) {
                uint32_t a[4];
                {
                    int ar = mi * 16 + (lane & 15);
                    ldsm_x4(a[0], a[1], a[2], a[3],
                            abase + ASWZ(ar, kt * 2 + (lane >> 4)));
                }
                uint32_t b[4][2];
                #pragma unroll
                for (int np = 0; np < 2; ++np) {
                    int br = nh * 32 + np * 16 + (lane & 7) + ((lane >> 4) << 3);
                    uint32_t r0, r1, r2, r3;
                    ldsm_x4(r0, r1, r2, r3,
                            bbase + ASWZ(br, kt * 2 + ((lane >> 3) & 1)));
                    b[np*2+0][0] = r0; b[np*2+0][1] = r1;
                    b[np*2+1][0] = r2; b[np*2+1][1] = r3;
                }
                #pragma unroll
                for (int nt = 0; nt < 4; ++nt)
                    mma_bf16(acc[nt], a, b[nt][0], b[nt][1]);
            }
        }

        /* ---- epilogue: divide, streaming store ---- */
        int r_lo = mi * 16 + (lane >> 2);
        int r_hi = r_lo + 8;
        float inv_lo = 1.0f / sden[r_lo];
        float inv_hi = 1.0f / sden[r_hi];
        float* obase = outg + ((size_t)head * SS + (size_t)s0) * DD;
        int c0 = nh * 32 + (lane & 3) * 2;
        #pragma unroll
        for (int nt = 0; nt < 4; ++nt) {
            __stcs((float2*)(obase + (size_t)r_lo * DD + nt * 8 + c0),
                   make_float2(acc[nt][0] * inv_lo, acc[nt][1] * inv_lo));
            __stcs((float2*)(obase + (size_t)r_hi * DD + nt * 8 + c0),
                   make_float2(acc[nt][2] * inv_hi, acc[nt][3] * inv_hi));
        }
    }
}

extern "C" void kernel_launch(void* const* d_in, const int* in_sizes, int n_in,
                              void* d_out, int out_size) {
    const float* q = (const float*)d_in[0];
    const float* k = (const float*)d_in[1];
    const float* v = (const float*)d_in[2];
    float* out = (float*)d_out;

    phase1_mma<<<NHEADS * SPLIT, 256>>>(k, v);
    reduce_k<<<NHEADS, 512>>>();
    phase2_mma<<<GRID2, 256>>>(q, out);
}